// round 2
// baseline (speedup 1.0000x reference)
#include <cuda_runtime.h>
#include <math.h>

// Problem constants
#define N_TOK 2048      // B*S
#define D_DIM 1024
#define E_EXP 8
#define I_DIM 1024      // per-expert intermediate (== IS)
#define TOPK  2

// GEMM tiling
#define TM 64
#define TN 64
#define TK 16

#define CAP (N_TOK*TOPK + E_EXP*TM)   // 4608: slots + per-expert padding
#define MAX_TILES (CAP/TM)            // 72

// ---------------- scratch (static device globals; no allocation) ----------------
__device__ float g_act[(size_t)CAP * I_DIM];        // routed silu(g)*u
__device__ float g_act_sh[(size_t)N_TOK * I_DIM];   // shared-expert silu(g)*u
__device__ float g_cr[(size_t)CAP * D_DIM];         // routed down-proj out (per slot)
__device__ float g_cs[(size_t)N_TOK * D_DIM];       // shared down-proj out (per token)
__device__ float g_topw[N_TOK*TOPK];
__device__ int   g_topi[N_TOK*TOPK];
__device__ int   g_counts[E_EXP];
__device__ int   g_off[E_EXP+1];
__device__ int   g_cursor[E_EXP];
__device__ int   g_slot_token[CAP];
__device__ int   g_token_slot[N_TOK*TOPK];
__device__ float g_psum[E_EXP];

// ---------------- init ----------------
__global__ void init_kernel() {
    int idx = blockIdx.x * blockDim.x + threadIdx.x;
    if (idx < CAP) g_slot_token[idx] = -1;
    if (idx < E_EXP) { g_counts[idx] = 0; g_psum[idx] = 0.f; }
}

// ---------------- router: logits, top-2, softmax weights, aux stats ----------------
__global__ void router_kernel(const float* __restrict__ x,
                              const float* __restrict__ wgate) {
    int warp = threadIdx.x >> 5;
    int lane = threadIdx.x & 31;
    int n = blockIdx.x * 8 + warp;
    if (n >= N_TOK) return;
    const float* xr = x + (size_t)n * D_DIM;

    float acc[E_EXP];
#pragma unroll
    for (int e = 0; e < E_EXP; e++) acc[e] = 0.f;
    for (int d = lane; d < D_DIM; d += 32) {
        float xv = xr[d];
        const float* w = wgate + (size_t)d * E_EXP;
#pragma unroll
        for (int e = 0; e < E_EXP; e++) acc[e] += xv * w[e];
    }
#pragma unroll
    for (int e = 0; e < E_EXP; e++) {
#pragma unroll
        for (int o = 16; o > 0; o >>= 1)
            acc[e] += __shfl_xor_sync(0xffffffffu, acc[e], o);
    }
    if (lane == 0) {
        // full softmax for P (aux loss)
        float m = acc[0];
#pragma unroll
        for (int e = 1; e < E_EXP; e++) m = fmaxf(m, acc[e]);
        float pe[E_EXP], se = 0.f;
#pragma unroll
        for (int e = 0; e < E_EXP; e++) { pe[e] = expf(acc[e] - m); se += pe[e]; }
        float inv = 1.f / se;
#pragma unroll
        for (int e = 0; e < E_EXP; e++) atomicAdd(&g_psum[e], pe[e] * inv);

        // top-2 (descending)
        int i0 = 0;
#pragma unroll
        for (int e = 1; e < E_EXP; e++) if (acc[e] > acc[i0]) i0 = e;
        int i1 = (i0 == 0) ? 1 : 0;
#pragma unroll
        for (int e = 0; e < E_EXP; e++) if (e != i0 && acc[e] > acc[i1]) i1 = e;

        float w0 = 1.f / (1.f + expf(acc[i1] - acc[i0]));  // softmax over {l0,l1}
        g_topi[n*2]   = i0;  g_topi[n*2+1] = i1;
        g_topw[n*2]   = w0;  g_topw[n*2+1] = 1.f - w0;
        atomicAdd(&g_counts[i0], 1);
        atomicAdd(&g_counts[i1], 1);
    }
}

// ---------------- prefix (TM-aligned bucket offsets) ----------------
__global__ void prefix_kernel() {
    if (threadIdx.x == 0 && blockIdx.x == 0) {
        int o = 0;
        for (int e = 0; e < E_EXP; e++) {
            g_off[e] = o;
            g_cursor[e] = o;
            o += ((g_counts[e] + TM - 1) / TM) * TM;
        }
        g_off[E_EXP] = o;
    }
}

// ---------------- scatter tokens into expert buckets ----------------
__global__ void scatter_kernel() {
    int n = blockIdx.x * blockDim.x + threadIdx.x;
    if (n >= N_TOK) return;
#pragma unroll
    for (int k = 0; k < TOPK; k++) {
        int e = g_topi[n*2 + k];
        int pos = atomicAdd(&g_cursor[e], 1);
        g_slot_token[pos] = n;
        g_token_slot[n*2 + k] = pos;
    }
}

// ---------------- fused gate+up GEMM (+SiLU*up epilogue) ----------------
// ROUTED=1: rows = slots (gathered x rows), weights indexed by bucket expert, out -> g_act
// ROUTED=0: rows = tokens, weights = shared expert, out -> g_act_sh
template<int ROUTED>
__global__ void gateup_kernel(const float* __restrict__ X,
                              const float* __restrict__ Wg,
                              const float* __restrict__ Wu) {
    __shared__ __align__(16) float As[TK][TM];
    __shared__ __align__(16) float B1[TK][TN];
    __shared__ __align__(16) float B2[TK][TN];
    __shared__ int s_tok[TM];

    int bm = blockIdx.x, bn = blockIdx.y;
    int row0 = bm * TM;
    const float *wg_e, *wu_e;
    if (ROUTED) {
        if (row0 >= g_off[E_EXP]) return;
        int e = 0;
#pragma unroll
        for (int q = 1; q < E_EXP; q++) if (row0 >= g_off[q]) e = q;
        wg_e = Wg + (size_t)e * D_DIM * I_DIM;
        wu_e = Wu + (size_t)e * D_DIM * I_DIM;
    } else {
        wg_e = Wg; wu_e = Wu;
    }

    int tid = threadIdx.x;
    if (tid < TM) s_tok[tid] = ROUTED ? g_slot_token[row0 + tid] : (row0 + tid);
    __syncthreads();

    int tx = tid & 15, ty = tid >> 4;
    int lm  = tid >> 2;          // A load: row within tile
    int lk  = (tid & 3) * 4;     // A load: k (float4)
    int ln  = tid & 63;          // B load: col
    int lk2 = tid >> 6;          // B load: k base
    int n0 = bn * TN;
    int tokA = s_tok[lm];

    float accg[4][4] = {}, accu[4][4] = {};

    for (int k0 = 0; k0 < D_DIM; k0 += TK) {
        float4 av = make_float4(0.f, 0.f, 0.f, 0.f);
        if (tokA >= 0)
            av = *(const float4*)&X[(size_t)tokA * D_DIM + k0 + lk];
        As[lk+0][lm] = av.x; As[lk+1][lm] = av.y;
        As[lk+2][lm] = av.z; As[lk+3][lm] = av.w;
#pragma unroll
        for (int r = 0; r < 4; r++) {
            int kk = lk2 + r * 4;
            B1[kk][ln] = wg_e[(size_t)(k0 + kk) * I_DIM + n0 + ln];
            B2[kk][ln] = wu_e[(size_t)(k0 + kk) * I_DIM + n0 + ln];
        }
        __syncthreads();
#pragma unroll
        for (int kk = 0; kk < TK; kk++) {
            float4 a  = *(const float4*)&As[kk][ty*4];
            float4 b1 = *(const float4*)&B1[kk][tx*4];
            float4 b2 = *(const float4*)&B2[kk][tx*4];
            float aa[4]  = {a.x, a.y, a.z, a.w};
            float bg[4]  = {b1.x, b1.y, b1.z, b1.w};
            float bu[4]  = {b2.x, b2.y, b2.z, b2.w};
#pragma unroll
            for (int i = 0; i < 4; i++)
#pragma unroll
                for (int j = 0; j < 4; j++) {
                    accg[i][j] += aa[i] * bg[j];
                    accu[i][j] += aa[i] * bu[j];
                }
        }
        __syncthreads();
    }

    float* Act = ROUTED ? g_act : g_act_sh;
#pragma unroll
    for (int i = 0; i < 4; i++) {
        int r = ty * 4 + i;
        if (s_tok[r] < 0) continue;
        size_t base = (size_t)(row0 + r) * I_DIM + n0 + tx * 4;
#pragma unroll
        for (int j = 0; j < 4; j++) {
            float g = accg[i][j];
            float a = g / (1.f + expf(-g)) * accu[i][j];   // silu(g)*u
            Act[base + j] = a;
        }
    }
}

// ---------------- down-proj GEMM ----------------
template<int ROUTED>
__global__ void down_kernel(const float* __restrict__ Wd) {
    __shared__ __align__(16) float As[TK][TM];
    __shared__ __align__(16) float Bs[TK][TN];

    int bm = blockIdx.x, bn = blockIdx.y;
    int row0 = bm * TM;
    const float* wd_e;
    const float* Ain;
    float* Cout;
    if (ROUTED) {
        if (row0 >= g_off[E_EXP]) return;
        int e = 0;
#pragma unroll
        for (int q = 1; q < E_EXP; q++) if (row0 >= g_off[q]) e = q;
        wd_e = Wd + (size_t)e * I_DIM * D_DIM;
        Ain = g_act; Cout = g_cr;
    } else {
        wd_e = Wd; Ain = g_act_sh; Cout = g_cs;
    }

    int tid = threadIdx.x;
    int tx = tid & 15, ty = tid >> 4;
    int lm  = tid >> 2;
    int lk  = (tid & 3) * 4;
    int ln  = tid & 63;
    int lk2 = tid >> 6;
    int n0 = bn * TN;

    float acc[4][4] = {};

    for (int k0 = 0; k0 < I_DIM; k0 += TK) {
        float4 av = *(const float4*)&Ain[(size_t)(row0 + lm) * I_DIM + k0 + lk];
        As[lk+0][lm] = av.x; As[lk+1][lm] = av.y;
        As[lk+2][lm] = av.z; As[lk+3][lm] = av.w;
#pragma unroll
        for (int r = 0; r < 4; r++) {
            int kk = lk2 + r * 4;
            Bs[kk][ln] = wd_e[(size_t)(k0 + kk) * D_DIM + n0 + ln];
        }
        __syncthreads();
#pragma unroll
        for (int kk = 0; kk < TK; kk++) {
            float4 a = *(const float4*)&As[kk][ty*4];
            float4 b = *(const float4*)&Bs[kk][tx*4];
            float aa[4] = {a.x, a.y, a.z, a.w};
            float bb[4] = {b.x, b.y, b.z, b.w};
#pragma unroll
            for (int i = 0; i < 4; i++)
#pragma unroll
                for (int j = 0; j < 4; j++)
                    acc[i][j] += aa[i] * bb[j];
        }
        __syncthreads();
    }

#pragma unroll
    for (int i = 0; i < 4; i++) {
        size_t base = (size_t)(row0 + ty*4 + i) * D_DIM + n0 + tx * 4;
#pragma unroll
        for (int j = 0; j < 4; j++)
            Cout[base + j] = acc[i][j];
    }
}

// ---------------- combine: out = shared + w0*routed(slot0) + w1*routed(slot1) ----------------
__global__ void combine_kernel(float* __restrict__ out) {
    int idx = blockIdx.x * blockDim.x + threadIdx.x;
    if (idx >= N_TOK * D_DIM) return;
    int n = idx >> 10;            // / D_DIM
    int d = idx & (D_DIM - 1);
    int s0 = g_token_slot[n*2], s1 = g_token_slot[n*2+1];
    float w0 = g_topw[n*2],     w1 = g_topw[n*2+1];
    out[idx] = g_cs[idx]
             + w0 * g_cr[(size_t)s0 * D_DIM + d]
             + w1 * g_cr[(size_t)s1 * D_DIM + d];
}

// ---------------- aux loss ----------------
__global__ void aux_kernel(float* __restrict__ out, int out_size) {
    if (threadIdx.x == 0 && blockIdx.x == 0) {
        float s = 0.f;
        float invN = 1.f / (float)N_TOK;
#pragma unroll
        for (int e = 0; e < E_EXP; e++)
            s += ((float)g_counts[e] * invN) * (g_psum[e] * invN);
        if (out_size > N_TOK * D_DIM)
            out[N_TOK * D_DIM] = (float)E_EXP * s;
    }
}

// ---------------- launch ----------------
extern "C" void kernel_launch(void* const* d_in, const int* in_sizes, int n_in,
                              void* d_out, int out_size) {
    const float* x     = (const float*)d_in[0];
    const float* wgate = (const float*)d_in[1];
    const float* wg    = (const float*)d_in[2];
    const float* wu    = (const float*)d_in[3];
    const float* wd    = (const float*)d_in[4];
    const float* wsg   = (const float*)d_in[5];
    const float* wsu   = (const float*)d_in[6];
    const float* wsd   = (const float*)d_in[7];
    float* out = (float*)d_out;

    init_kernel<<<(CAP + 255) / 256, 256>>>();
    router_kernel<<<N_TOK / 8, 256>>>(x, wgate);
    prefix_kernel<<<1, 32>>>();
    scatter_kernel<<<(N_TOK + 255) / 256, 256>>>();

    dim3 gridRoutedGU(MAX_TILES, I_DIM / TN);
    gateup_kernel<1><<<gridRoutedGU, 256>>>(x, wg, wu);

    dim3 gridSharedGU(N_TOK / TM, I_DIM / TN);
    gateup_kernel<0><<<gridSharedGU, 256>>>(x, wsg, wsu);

    dim3 gridRoutedD(MAX_TILES, D_DIM / TN);
    down_kernel<1><<<gridRoutedD, 256>>>(wd);

    dim3 gridSharedD(N_TOK / TM, D_DIM / TN);
    down_kernel<0><<<gridSharedD, 256>>>(wsd);

    combine_kernel<<<(N_TOK * D_DIM + 255) / 256, 256>>>(out);
    aux_kernel<<<1, 32>>>(out, out_size);
}

// round 3
// speedup vs baseline: 1.0005x; 1.0005x over previous
#include <cuda_runtime.h>
#include <math.h>

// Problem constants
#define N_TOK 2048      // B*S
#define D_DIM 1024
#define E_EXP 8
#define I_DIM 1024      // per-expert intermediate (== IS)
#define TOPK  2

// GEMM tiling
#define TM 64
#define TN 64
#define TK 16

#define CAP (N_TOK*TOPK + E_EXP*TM)   // 4608: slots + per-expert padding
#define MAX_TILES (CAP/TM)            // 72

// ---------------- scratch (static device globals; no allocation) ----------------
__device__ float g_act[(size_t)CAP * I_DIM];        // routed silu(g)*u
__device__ float g_act_sh[(size_t)N_TOK * I_DIM];   // shared-expert silu(g)*u
__device__ float g_cr[(size_t)CAP * D_DIM];         // routed down-proj out (per slot)
__device__ float g_cs[(size_t)N_TOK * D_DIM];       // shared down-proj out (per token)
__device__ float g_topw[N_TOK*TOPK];
__device__ int   g_topi[N_TOK*TOPK];
__device__ int   g_counts[E_EXP];
__device__ int   g_off[E_EXP+1];
__device__ int   g_cursor[E_EXP];
__device__ int   g_slot_token[CAP];
__device__ int   g_token_slot[N_TOK*TOPK];
__device__ float g_psum[E_EXP];

// ---------------- init ----------------
__global__ void init_kernel() {
    int idx = blockIdx.x * blockDim.x + threadIdx.x;
    if (idx < CAP) g_slot_token[idx] = -1;
    if (idx < E_EXP) { g_counts[idx] = 0; g_psum[idx] = 0.f; }
}

// ---------------- router: logits, top-2, softmax weights, aux stats ----------------
__global__ void router_kernel(const float* __restrict__ x,
                              const float* __restrict__ wgate) {
    int warp = threadIdx.x >> 5;
    int lane = threadIdx.x & 31;
    int n = blockIdx.x * 8 + warp;
    if (n >= N_TOK) return;
    const float* xr = x + (size_t)n * D_DIM;

    float acc[E_EXP];
#pragma unroll
    for (int e = 0; e < E_EXP; e++) acc[e] = 0.f;
    for (int d = lane; d < D_DIM; d += 32) {
        float xv = xr[d];
        const float* w = wgate + (size_t)d * E_EXP;
#pragma unroll
        for (int e = 0; e < E_EXP; e++) acc[e] += xv * w[e];
    }
#pragma unroll
    for (int e = 0; e < E_EXP; e++) {
#pragma unroll
        for (int o = 16; o > 0; o >>= 1)
            acc[e] += __shfl_xor_sync(0xffffffffu, acc[e], o);
    }
    if (lane == 0) {
        // full softmax for P (aux loss)
        float m = acc[0];
#pragma unroll
        for (int e = 1; e < E_EXP; e++) m = fmaxf(m, acc[e]);
        float pe[E_EXP], se = 0.f;
#pragma unroll
        for (int e = 0; e < E_EXP; e++) { pe[e] = expf(acc[e] - m); se += pe[e]; }
        float inv = 1.f / se;
#pragma unroll
        for (int e = 0; e < E_EXP; e++) atomicAdd(&g_psum[e], pe[e] * inv);

        // top-2 (descending)
        int i0 = 0;
#pragma unroll
        for (int e = 1; e < E_EXP; e++) if (acc[e] > acc[i0]) i0 = e;
        int i1 = (i0 == 0) ? 1 : 0;
#pragma unroll
        for (int e = 0; e < E_EXP; e++) if (e != i0 && acc[e] > acc[i1]) i1 = e;

        float w0 = 1.f / (1.f + expf(acc[i1] - acc[i0]));  // softmax over {l0,l1}
        g_topi[n*2]   = i0;  g_topi[n*2+1] = i1;
        g_topw[n*2]   = w0;  g_topw[n*2+1] = 1.f - w0;
        atomicAdd(&g_counts[i0], 1);
        atomicAdd(&g_counts[i1], 1);
    }
}

// ---------------- prefix (TM-aligned bucket offsets) ----------------
__global__ void prefix_kernel() {
    if (threadIdx.x == 0 && blockIdx.x == 0) {
        int o = 0;
        for (int e = 0; e < E_EXP; e++) {
            g_off[e] = o;
            g_cursor[e] = o;
            o += ((g_counts[e] + TM - 1) / TM) * TM;
        }
        g_off[E_EXP] = o;
    }
}

// ---------------- scatter tokens into expert buckets ----------------
__global__ void scatter_kernel() {
    int n = blockIdx.x * blockDim.x + threadIdx.x;
    if (n >= N_TOK) return;
#pragma unroll
    for (int k = 0; k < TOPK; k++) {
        int e = g_topi[n*2 + k];
        int pos = atomicAdd(&g_cursor[e], 1);
        g_slot_token[pos] = n;
        g_token_slot[n*2 + k] = pos;
    }
}

// ---------------- fused gate+up GEMM (+SiLU*up epilogue) ----------------
// ROUTED=1: rows = slots (gathered x rows), weights indexed by bucket expert, out -> g_act
// ROUTED=0: rows = tokens, weights = shared expert, out -> g_act_sh
template<int ROUTED>
__global__ void gateup_kernel(const float* __restrict__ X,
                              const float* __restrict__ Wg,
                              const float* __restrict__ Wu) {
    __shared__ __align__(16) float As[TK][TM];
    __shared__ __align__(16) float B1[TK][TN];
    __shared__ __align__(16) float B2[TK][TN];
    __shared__ int s_tok[TM];

    int bm = blockIdx.x, bn = blockIdx.y;
    int row0 = bm * TM;
    const float *wg_e, *wu_e;
    if (ROUTED) {
        if (row0 >= g_off[E_EXP]) return;
        int e = 0;
#pragma unroll
        for (int q = 1; q < E_EXP; q++) if (row0 >= g_off[q]) e = q;
        wg_e = Wg + (size_t)e * D_DIM * I_DIM;
        wu_e = Wu + (size_t)e * D_DIM * I_DIM;
    } else {
        wg_e = Wg; wu_e = Wu;
    }

    int tid = threadIdx.x;
    if (tid < TM) s_tok[tid] = ROUTED ? g_slot_token[row0 + tid] : (row0 + tid);
    __syncthreads();

    int tx = tid & 15, ty = tid >> 4;
    int lm  = tid >> 2;          // A load: row within tile
    int lk  = (tid & 3) * 4;     // A load: k (float4)
    int ln  = tid & 63;          // B load: col
    int lk2 = tid >> 6;          // B load: k base
    int n0 = bn * TN;
    int tokA = s_tok[lm];

    float accg[4][4] = {}, accu[4][4] = {};

    for (int k0 = 0; k0 < D_DIM; k0 += TK) {
        float4 av = make_float4(0.f, 0.f, 0.f, 0.f);
        if (tokA >= 0)
            av = *(const float4*)&X[(size_t)tokA * D_DIM + k0 + lk];
        As[lk+0][lm] = av.x; As[lk+1][lm] = av.y;
        As[lk+2][lm] = av.z; As[lk+3][lm] = av.w;
#pragma unroll
        for (int r = 0; r < 4; r++) {
            int kk = lk2 + r * 4;
            B1[kk][ln] = wg_e[(size_t)(k0 + kk) * I_DIM + n0 + ln];
            B2[kk][ln] = wu_e[(size_t)(k0 + kk) * I_DIM + n0 + ln];
        }
        __syncthreads();
#pragma unroll
        for (int kk = 0; kk < TK; kk++) {
            float4 a  = *(const float4*)&As[kk][ty*4];
            float4 b1 = *(const float4*)&B1[kk][tx*4];
            float4 b2 = *(const float4*)&B2[kk][tx*4];
            float aa[4]  = {a.x, a.y, a.z, a.w};
            float bg[4]  = {b1.x, b1.y, b1.z, b1.w};
            float bu[4]  = {b2.x, b2.y, b2.z, b2.w};
#pragma unroll
            for (int i = 0; i < 4; i++)
#pragma unroll
                for (int j = 0; j < 4; j++) {
                    accg[i][j] += aa[i] * bg[j];
                    accu[i][j] += aa[i] * bu[j];
                }
        }
        __syncthreads();
    }

    float* Act = ROUTED ? g_act : g_act_sh;
#pragma unroll
    for (int i = 0; i < 4; i++) {
        int r = ty * 4 + i;
        if (s_tok[r] < 0) continue;
        size_t base = (size_t)(row0 + r) * I_DIM + n0 + tx * 4;
#pragma unroll
        for (int j = 0; j < 4; j++) {
            float g = accg[i][j];
            float a = g / (1.f + expf(-g)) * accu[i][j];   // silu(g)*u
            Act[base + j] = a;
        }
    }
}

// ---------------- down-proj GEMM ----------------
template<int ROUTED>
__global__ void down_kernel(const float* __restrict__ Wd) {
    __shared__ __align__(16) float As[TK][TM];
    __shared__ __align__(16) float Bs[TK][TN];

    int bm = blockIdx.x, bn = blockIdx.y;
    int row0 = bm * TM;
    const float* wd_e;
    const float* Ain;
    float* Cout;
    if (ROUTED) {
        if (row0 >= g_off[E_EXP]) return;
        int e = 0;
#pragma unroll
        for (int q = 1; q < E_EXP; q++) if (row0 >= g_off[q]) e = q;
        wd_e = Wd + (size_t)e * I_DIM * D_DIM;
        Ain = g_act; Cout = g_cr;
    } else {
        wd_e = Wd; Ain = g_act_sh; Cout = g_cs;
    }

    int tid = threadIdx.x;
    int tx = tid & 15, ty = tid >> 4;
    int lm  = tid >> 2;
    int lk  = (tid & 3) * 4;
    int ln  = tid & 63;
    int lk2 = tid >> 6;
    int n0 = bn * TN;

    float acc[4][4] = {};

    for (int k0 = 0; k0 < I_DIM; k0 += TK) {
        float4 av = *(const float4*)&Ain[(size_t)(row0 + lm) * I_DIM + k0 + lk];
        As[lk+0][lm] = av.x; As[lk+1][lm] = av.y;
        As[lk+2][lm] = av.z; As[lk+3][lm] = av.w;
#pragma unroll
        for (int r = 0; r < 4; r++) {
            int kk = lk2 + r * 4;
            Bs[kk][ln] = wd_e[(size_t)(k0 + kk) * D_DIM + n0 + ln];
        }
        __syncthreads();
#pragma unroll
        for (int kk = 0; kk < TK; kk++) {
            float4 a = *(const float4*)&As[kk][ty*4];
            float4 b = *(const float4*)&Bs[kk][tx*4];
            float aa[4] = {a.x, a.y, a.z, a.w};
            float bb[4] = {b.x, b.y, b.z, b.w};
#pragma unroll
            for (int i = 0; i < 4; i++)
#pragma unroll
                for (int j = 0; j < 4; j++)
                    acc[i][j] += aa[i] * bb[j];
        }
        __syncthreads();
    }

#pragma unroll
    for (int i = 0; i < 4; i++) {
        size_t base = (size_t)(row0 + ty*4 + i) * D_DIM + n0 + tx * 4;
#pragma unroll
        for (int j = 0; j < 4; j++)
            Cout[base + j] = acc[i][j];
    }
}

// ---------------- combine: out = shared + w0*routed(slot0) + w1*routed(slot1) ----------------
__global__ void combine_kernel(float* __restrict__ out) {
    int idx = blockIdx.x * blockDim.x + threadIdx.x;
    if (idx >= N_TOK * D_DIM) return;
    int n = idx >> 10;            // / D_DIM
    int d = idx & (D_DIM - 1);
    int s0 = g_token_slot[n*2], s1 = g_token_slot[n*2+1];
    float w0 = g_topw[n*2],     w1 = g_topw[n*2+1];
    out[idx] = g_cs[idx]
             + w0 * g_cr[(size_t)s0 * D_DIM + d]
             + w1 * g_cr[(size_t)s1 * D_DIM + d];
}

// ---------------- aux loss ----------------
__global__ void aux_kernel(float* __restrict__ out, int out_size) {
    if (threadIdx.x == 0 && blockIdx.x == 0) {
        float s = 0.f;
        float invN = 1.f / (float)N_TOK;
#pragma unroll
        for (int e = 0; e < E_EXP; e++)
            s += ((float)g_counts[e] * invN) * (g_psum[e] * invN);
        if (out_size > N_TOK * D_DIM)
            out[N_TOK * D_DIM] = (float)E_EXP * s;
    }
}

// ---------------- launch ----------------
extern "C" void kernel_launch(void* const* d_in, const int* in_sizes, int n_in,
                              void* d_out, int out_size) {
    const float* x     = (const float*)d_in[0];
    const float* wgate = (const float*)d_in[1];
    const float* wg    = (const float*)d_in[2];
    const float* wu    = (const float*)d_in[3];
    const float* wd    = (const float*)d_in[4];
    const float* wsg   = (const float*)d_in[5];
    const float* wsu   = (const float*)d_in[6];
    const float* wsd   = (const float*)d_in[7];
    float* out = (float*)d_out;

    init_kernel<<<(CAP + 255) / 256, 256>>>();
    router_kernel<<<N_TOK / 8, 256>>>(x, wgate);
    prefix_kernel<<<1, 32>>>();
    scatter_kernel<<<(N_TOK + 255) / 256, 256>>>();

    dim3 gridRoutedGU(MAX_TILES, I_DIM / TN);
    gateup_kernel<1><<<gridRoutedGU, 256>>>(x, wg, wu);

    dim3 gridSharedGU(N_TOK / TM, I_DIM / TN);
    gateup_kernel<0><<<gridSharedGU, 256>>>(x, wsg, wsu);

    dim3 gridRoutedD(MAX_TILES, D_DIM / TN);
    down_kernel<1><<<gridRoutedD, 256>>>(wd);

    dim3 gridSharedD(N_TOK / TM, D_DIM / TN);
    down_kernel<0><<<gridSharedD, 256>>>(wsd);

    combine_kernel<<<(N_TOK * D_DIM + 255) / 256, 256>>>(out);
    aux_kernel<<<1, 32>>>(out, out_size);
}